// round 7
// baseline (speedup 1.0000x reference)
#include <cuda_runtime.h>
#include <cuda_fp16.h>

#define NBODY 4194304
#define NMASK (NBODY / 32)
#define MAXPART 16384
#define HALF_PI 1.57079632679489662f

// Scratch — __device__ globals. g_cnt is zero at load; K2c re-zeroes it each
// call. g_mask/g_rec/g_part are fully overwritten each call. Replay-safe.
__device__ unsigned int g_cnt[NBODY];    // per-body endpoint counts
__device__ unsigned int g_rec[NBODY];    // {f16 ax | f16 ay}
__device__ unsigned int g_mask[NMASK];   // touched bitmask (1 bit/body)
__device__ float4       g_part[MAXPART]; // per-block partial sums
__device__ float4       g_target;        // {tx, ty, stiffness*DT, 0}

// ---------------------------------------------------------------------------
// K1: count-scatter histogram. int4 loads, 8 fire-and-forget RED.ADD.u32 per
// thread into spread addresses. L2-atomic-bound (~25 us). Runs on stream 2,
// concurrent with K2 (which doesn't touch g_cnt).
// ---------------------------------------------------------------------------
__global__ void __launch_bounds__(256)
k1_scatter(const int4* __restrict__ fromb4,
           const int4* __restrict__ tob4,
           const int*  __restrict__ fromb,
           const int*  __restrict__ tob,
           int nc) {
    int i = blockIdx.x * blockDim.x + threadIdx.x;
    int n4 = nc >> 2;
    if (i < n4) {
        int4 a = fromb4[i];
        int4 b = tob4[i];
        atomicAdd(&g_cnt[a.x], 1u);
        atomicAdd(&g_cnt[a.y], 1u);
        atomicAdd(&g_cnt[a.z], 1u);
        atomicAdd(&g_cnt[a.w], 1u);
        atomicAdd(&g_cnt[b.x], 1u);
        atomicAdd(&g_cnt[b.y], 1u);
        atomicAdd(&g_cnt[b.z], 1u);
        atomicAdd(&g_cnt[b.w], 1u);
    } else {
        int j = (n4 << 2) + (i - n4);            // tail (nc % 4)
        if (j < nc) {
            atomicAdd(&g_cnt[fromb[j]], 1u);
            atomicAdd(&g_cnt[tob[j]],   1u);
        }
    }
}

// ---------------------------------------------------------------------------
// K2: pure streaming record build, 2 bodies/thread. Independent of g_cnt.
// Reads pos/ang/rel once (84 MB), writes 4B f16 record per body (17 MB).
// ---------------------------------------------------------------------------
__global__ void __launch_bounds__(256)
k2_build(const float4* __restrict__ pos2,
         const float2* __restrict__ ang2,
         const float2* __restrict__ fpos,
         const float2* __restrict__ tpos,
         int n, int nc) {
    int i = blockIdx.x * blockDim.x + threadIdx.x;
    int b0 = 2 * i, b1 = b0 + 1;
    if (b0 >= n) return;

    float4 p  = pos2[i];
    float2 a2 = ang2[i];

    float2 r0 = (b0 < nc) ? fpos[b0] : tpos[b0 - nc];
    float2 r1 = (b1 < n) ? ((b1 < nc) ? fpos[b1] : tpos[b1 - nc])
                         : make_float2(0.0f, 0.0f);

    float s0, c0, s1, c1;
    __sincosf(a2.x - HALF_PI, &s0, &c0);
    __sincosf(a2.y - HALF_PI, &s1, &c1);

    float ax0 = fmaf(c0, r0.x, fmaf(-s0, r0.y, p.x));
    float ay0 = fmaf(s0, r0.x, fmaf( c0, r0.y, p.y));
    float ax1 = fmaf(c1, r1.x, fmaf(-s1, r1.y, p.z));
    float ay1 = fmaf(s1, r1.x, fmaf( c1, r1.y, p.w));

    unsigned int w0 = (unsigned int)__half_as_ushort(__float2half_rn(ax0))
                    | ((unsigned int)__half_as_ushort(__float2half_rn(ay0)) << 16);
    unsigned int w1 = (unsigned int)__half_as_ushort(__float2half_rn(ax1))
                    | ((unsigned int)__half_as_ushort(__float2half_rn(ay1)) << 16);

    if (b1 < n) ((uint2*)g_rec)[i] = make_uint2(w0, w1);
    else        g_rec[b0] = w0;
}

// ---------------------------------------------------------------------------
// K2c: cnt-dependent pass (runs after K1 AND K2). One body/thread:
// read cnt, zero it, ballot the touched bit into the 0.5 MB bitmask,
// accumulate cnt*m*{ax,ay,1} into one plain float4 partial per block.
// ---------------------------------------------------------------------------
__global__ void __launch_bounds__(256)
k2c_sums(const float* __restrict__ mass, int n) {
    int b = blockIdx.x * blockDim.x + threadIdx.x;
    bool in = (b < n);

    unsigned int cnt = 0u;
    if (in) {
        cnt = g_cnt[b];
        g_cnt[b] = 0u;                        // restore replay state
    }

    // touched bitmask: one u32 store per warp (b of lane 0 is 32-aligned)
    unsigned int bal = __ballot_sync(0xffffffffu, in && cnt != 0u);
    if ((threadIdx.x & 31) == 0 && in) g_mask[b >> 5] = bal;

    float sx = 0.0f, sy = 0.0f, sm = 0.0f;
    if (in) {
        unsigned int rc = g_rec[b];
        float ax = __half2float(__ushort_as_half((unsigned short)(rc & 0xffffu)));
        float ay = __half2float(__ushort_as_half((unsigned short)(rc >> 16)));
        float cm = (float)cnt * mass[b];
        sx = cm * ax;
        sy = cm * ay;
        sm = cm;
    }

    #pragma unroll
    for (int o = 16; o > 0; o >>= 1) {
        sx += __shfl_down_sync(0xffffffffu, sx, o);
        sy += __shfl_down_sync(0xffffffffu, sy, o);
        sm += __shfl_down_sync(0xffffffffu, sm, o);
    }

    __shared__ float ssx[8], ssy[8], ssm[8];
    int wid = threadIdx.x >> 5, lid = threadIdx.x & 31;
    if (lid == 0) { ssx[wid] = sx; ssy[wid] = sy; ssm[wid] = sm; }
    __syncthreads();

    if (threadIdx.x == 0) {
        float tx = 0.0f, ty = 0.0f, tm = 0.0f;
        #pragma unroll
        for (int w = 0; w < 8; ++w) { tx += ssx[w]; ty += ssy[w]; tm += ssm[w]; }
        g_part[blockIdx.x] = make_float4(tx, ty, tm, 0.0f);   // plain store
    }
}

// ---------------------------------------------------------------------------
// K2b: single-block finalize of the partials (256 KB) in double.
// ---------------------------------------------------------------------------
__global__ void __launch_bounds__(1024)
k2b_finalize(const float* __restrict__ stiff, int nparts) {
    double sx = 0.0, sy = 0.0, sm = 0.0;
    for (int i = threadIdx.x; i < nparts; i += 1024) {
        float4 p = g_part[i];
        sx += (double)p.x; sy += (double)p.y; sm += (double)p.z;
    }
    #pragma unroll
    for (int o = 16; o > 0; o >>= 1) {
        sx += __shfl_down_sync(0xffffffffu, sx, o);
        sy += __shfl_down_sync(0xffffffffu, sy, o);
        sm += __shfl_down_sync(0xffffffffu, sm, o);
    }
    __shared__ double dsx[32], dsy[32], dsm[32];
    int wid = threadIdx.x >> 5, lid = threadIdx.x & 31;
    if (lid == 0) { dsx[wid] = sx; dsy[wid] = sy; dsm[wid] = sm; }
    __syncthreads();
    if (threadIdx.x == 0) {
        double tx = 0.0, ty = 0.0, tm = 0.0;
        #pragma unroll
        for (int w = 0; w < 32; ++w) { tx += dsx[w]; ty += dsy[w]; tm += dsm[w]; }
        g_target = make_float4((float)(tx / tm), (float)(ty / tm),
                               stiff[0] * 0.01f, 0.0f);
    }
}

// ---------------------------------------------------------------------------
// K3: vectorized epilogue, 2 bodies/thread. rec 17 + mask 0.5 + vel 33 +
// out 33 = 84 MB.
// ---------------------------------------------------------------------------
__global__ void __launch_bounds__(256)
k3_apply(const float4* __restrict__ vel2,
         float4*       __restrict__ out2,
         int nhalf) {
    int i = blockIdx.x * blockDim.x + threadIdx.x;
    if (i >= nhalf) return;

    float4 t = g_target;                         // uniform broadcast
    unsigned int mw = g_mask[i >> 4];            // word for bodies 2i, 2i+1
    uint2  rc = ((const uint2*)g_rec)[i];
    float4 v  = vel2[i];

    int bit0 = (2 * i) & 31;
    {
        float ax = __half2float(__ushort_as_half((unsigned short)(rc.x & 0xffffu)));
        float ay = __half2float(__ushort_as_half((unsigned short)(rc.x >> 16)));
        float f  = ((mw >> bit0) & 1u) ? t.z : 0.0f;
        v.x = fmaf(f, t.x - ax, v.x);
        v.y = fmaf(f, t.y - ay, v.y);
    }
    {
        float ax = __half2float(__ushort_as_half((unsigned short)(rc.y & 0xffffu)));
        float ay = __half2float(__ushort_as_half((unsigned short)(rc.y >> 16)));
        float f  = ((mw >> (bit0 + 1)) & 1u) ? t.z : 0.0f;
        v.z = fmaf(f, t.x - ax, v.z);
        v.w = fmaf(f, t.y - ay, v.w);
    }
    out2[i] = v;
}

__global__ void __launch_bounds__(256)
k3_apply_tail(const float2* __restrict__ vel,
              float2*       __restrict__ out,
              int start, int n) {
    int b = start + blockIdx.x * blockDim.x + threadIdx.x;
    if (b >= n) return;
    float4 t = g_target;
    unsigned int rc = g_rec[b];
    float ax = __half2float(__ushort_as_half((unsigned short)(rc & 0xffffu)));
    float ay = __half2float(__ushort_as_half((unsigned short)(rc >> 16)));
    float f  = ((g_mask[b >> 5] >> (b & 31)) & 1u) ? t.z : 0.0f;
    float2 v = vel[b];
    v.x = fmaf(f, t.x - ax, v.x);
    v.y = fmaf(f, t.y - ay, v.y);
    out[b] = v;
}

// ---------------------------------------------------------------------------
// Inputs: from_bodies, to_bodies, from_bodies_position, to_bodies_position,
//         stiffness, position, angle, mass, velocity
// ---------------------------------------------------------------------------
extern "C" void kernel_launch(void* const* d_in, const int* in_sizes, int n_in,
                              void* d_out, int out_size) {
    const int*    fromb = (const int*)   d_in[0];
    const int*    tob   = (const int*)   d_in[1];
    const float2* fpos  = (const float2*)d_in[2];
    const float2* tpos  = (const float2*)d_in[3];
    const float*  stiff = (const float*) d_in[4];
    const float2* pos   = (const float2*)d_in[5];
    const float*  ang   = (const float*) d_in[6];
    const float*  mass  = (const float*) d_in[7];
    const float2* vel   = (const float2*)d_in[8];

    int nc = in_sizes[0];
    int n  = in_sizes[6];
    if (n > NBODY) n = NBODY;

    const int tpb = 256;
    int n4    = nc >> 2;
    int k1t   = n4 + (nc & 3);
    int nb1   = (k1t + tpb - 1) / tpb;
    int npair = (n + 1) >> 1;
    int nb2   = (npair + tpb - 1) / tpb;
    int nb2c  = (n + tpb - 1) / tpb;
    if (nb2c > MAXPART) nb2c = MAXPART;          // n<=NBODY guarantees fit
    int half  = n >> 1;
    int nb3   = (half + tpb - 1) / tpb;

    // One-time host-resource init (first call happens before graph capture).
    static cudaStream_t s2 = 0;
    static cudaEvent_t  evFork = 0, evJoin = 0;
    static int          initState = 0;           // 0=uninit, 1=ok, -1=fallback
    if (initState == 0) {
        if (cudaStreamCreateWithFlags(&s2, cudaStreamNonBlocking) == cudaSuccess &&
            cudaEventCreateWithFlags(&evFork, cudaEventDisableTiming) == cudaSuccess &&
            cudaEventCreateWithFlags(&evJoin, cudaEventDisableTiming) == cudaSuccess)
            initState = 1;
        else
            initState = -1;
    }

    if (initState == 1) {
        // Fork: K1 (atomic histogram) on s2, concurrent with K2 (stream build).
        cudaEventRecord(evFork, 0);
        cudaStreamWaitEvent(s2, evFork, 0);
        k1_scatter<<<nb1, tpb, 0, s2>>>((const int4*)fromb, (const int4*)tob,
                                        fromb, tob, nc);
        cudaEventRecord(evJoin, s2);

        k2_build<<<nb2, tpb>>>((const float4*)pos, (const float2*)ang,
                               fpos, tpos, n, nc);

        // Join back into the main stream before the cnt-dependent pass.
        cudaStreamWaitEvent(0, evJoin, 0);
    } else {
        // Serial fallback (no second stream available).
        k1_scatter<<<nb1, tpb>>>((const int4*)fromb, (const int4*)tob,
                                 fromb, tob, nc);
        k2_build<<<nb2, tpb>>>((const float4*)pos, (const float2*)ang,
                               fpos, tpos, n, nc);
    }

    k2c_sums<<<nb2c, tpb>>>(mass, n);
    k2b_finalize<<<1, 1024>>>(stiff, nb2c);
    if (half > 0)
        k3_apply<<<nb3, tpb>>>((const float4*)vel, (float4*)d_out, half);
    if (n & 1)
        k3_apply_tail<<<1, tpb>>>(vel, (float2*)d_out, n - 1, n);
}

// round 8
// speedup vs baseline: 1.2315x; 1.2315x over previous
#include <cuda_runtime.h>
#include <cuda_fp16.h>

#define NBODY 4194304
#define NMASK (NBODY / 32)
#define NPART 1184
#define HALF_PI 1.57079632679489662f

// Scratch — __device__ globals. g_cnt is zero at load; KB re-zeroes it each
// call. g_rec/g_mask/g_part fully overwritten each call. Replay-safe.
__device__ unsigned int g_cnt[NBODY];   // per-body endpoint counts
__device__ unsigned int g_rec[NBODY];   // {f16 ax | f16 ay}
__device__ unsigned int g_mask[NMASK];  // touched bitmask (1 bit/body)
__device__ float4       g_part[NPART];  // per-block partial sums
__device__ float4       g_target;       // {tx, ty, stiffness*DT, 0}

// ---------------------------------------------------------------------------
// KA (fused): thread i handles bodies 2i,2i+1 (streaming record build) AND
// endpoints 2i,2i+1 (one coalesced int2 index load + 2 fire-and-forget
// RED.ADD.u32). Intra-kernel overlap of DRAM streaming with L2 atomics
// (measured cheaper than running them as separate kernels).
// nc is even, so an endpoint pair never straddles the from/to concat boundary.
// ---------------------------------------------------------------------------
__global__ void __launch_bounds__(256)
ka_build_scatter(const float4* __restrict__ pos2,
                 const float2* __restrict__ ang2,
                 const float2* __restrict__ fpos,
                 const float2* __restrict__ tpos,
                 const int2*   __restrict__ fromb2,
                 const int2*   __restrict__ tob2,
                 int n, int nc) {
    int i = blockIdx.x * blockDim.x + threadIdx.x;
    int b0 = 2 * i, b1 = b0 + 1;

    if (b0 < n) {
        float4 p  = pos2[i];
        float2 a2 = ang2[i];

        // rel = concat(from_pos, to_pos), indexed by BODY index
        float2 r0 = (b0 < nc) ? fpos[b0] : tpos[b0 - nc];
        float2 r1 = (b1 < n) ? ((b1 < nc) ? fpos[b1] : tpos[b1 - nc])
                             : make_float2(0.0f, 0.0f);

        float s0, c0, s1, c1;
        __sincosf(a2.x - HALF_PI, &s0, &c0);
        __sincosf(a2.y - HALF_PI, &s1, &c1);

        float ax0 = fmaf(c0, r0.x, fmaf(-s0, r0.y, p.x));
        float ay0 = fmaf(s0, r0.x, fmaf( c0, r0.y, p.y));
        float ax1 = fmaf(c1, r1.x, fmaf(-s1, r1.y, p.z));
        float ay1 = fmaf(s1, r1.x, fmaf( c1, r1.y, p.w));

        unsigned int w0 = (unsigned int)__half_as_ushort(__float2half_rn(ax0))
                        | ((unsigned int)__half_as_ushort(__float2half_rn(ay0)) << 16);
        unsigned int w1 = (unsigned int)__half_as_ushort(__float2half_rn(ax1))
                        | ((unsigned int)__half_as_ushort(__float2half_rn(ay1)) << 16);

        if (b1 < n) ((uint2*)g_rec)[i] = make_uint2(w0, w1);
        else        g_rec[b0] = w0;
    }

    // endpoint pair 2i, 2i+1 of concat(fromb, tob): 2*nc endpoints total
    int nch = nc >> 1;                    // int2 pairs per side
    if (i < nch) {
        int2 e = fromb2[i];
        atomicAdd(&g_cnt[e.x], 1u);       // return unused -> RED
        atomicAdd(&g_cnt[e.y], 1u);
    } else if (i < 2 * nch) {
        int2 e = tob2[i - nch];
        atomicAdd(&g_cnt[e.x], 1u);
        atomicAdd(&g_cnt[e.y], 1u);
    }
    // (nc is even in this problem; no scalar tail needed for 2*nc endpoints)
}

// ---------------------------------------------------------------------------
// KB: cnt-dependent pass, grid-stride over bodies with NPART blocks.
// Read cnt, zero it, ballot touched bit into 0.5 MB bitmask, accumulate
// cnt*m*{ax,ay,1}; one plain float4 partial per block. No atomics.
// ---------------------------------------------------------------------------
__global__ void __launch_bounds__(256)
kb_sums(const float* __restrict__ mass, int n) {
    const int stride = gridDim.x * blockDim.x;
    // pad loop bound to a stride multiple so all warp lanes iterate together
    int nloop = ((n + stride - 1) / stride) * stride;

    float sx = 0.0f, sy = 0.0f, sm = 0.0f;

    for (int i = blockIdx.x * blockDim.x + threadIdx.x; i < nloop; i += stride) {
        bool in = (i < n);
        unsigned int cnt = 0u;
        if (in) {
            cnt = g_cnt[i];
            g_cnt[i] = 0u;                       // restore replay state
        }
        unsigned int bal = __ballot_sync(0xffffffffu, in && cnt != 0u);
        if ((threadIdx.x & 31) == 0 && in) g_mask[i >> 5] = bal;

        if (in) {
            unsigned int rc = g_rec[i];
            float ax = __half2float(__ushort_as_half((unsigned short)(rc & 0xffffu)));
            float ay = __half2float(__ushort_as_half((unsigned short)(rc >> 16)));
            float cm = (float)cnt * mass[i];
            sx = fmaf(cm, ax, sx);
            sy = fmaf(cm, ay, sy);
            sm += cm;
        }
    }

    #pragma unroll
    for (int o = 16; o > 0; o >>= 1) {
        sx += __shfl_down_sync(0xffffffffu, sx, o);
        sy += __shfl_down_sync(0xffffffffu, sy, o);
        sm += __shfl_down_sync(0xffffffffu, sm, o);
    }

    __shared__ float ssx[8], ssy[8], ssm[8];
    int wid = threadIdx.x >> 5, lid = threadIdx.x & 31;
    if (lid == 0) { ssx[wid] = sx; ssy[wid] = sy; ssm[wid] = sm; }
    __syncthreads();

    if (threadIdx.x == 0) {
        float tx = 0.0f, ty = 0.0f, tm = 0.0f;
        #pragma unroll
        for (int w = 0; w < 8; ++w) { tx += ssx[w]; ty += ssy[w]; tm += ssm[w]; }
        g_part[blockIdx.x] = make_float4(tx, ty, tm, 0.0f);    // plain store
    }
}

// ---------------------------------------------------------------------------
// KC: single-block finalize over NPART partials (19 KB) in double. ~2 us.
// ---------------------------------------------------------------------------
__global__ void __launch_bounds__(1024)
kc_finalize(const float* __restrict__ stiff, int nparts) {
    double sx = 0.0, sy = 0.0, sm = 0.0;
    for (int i = threadIdx.x; i < nparts; i += 1024) {
        float4 p = g_part[i];
        sx += (double)p.x; sy += (double)p.y; sm += (double)p.z;
    }
    #pragma unroll
    for (int o = 16; o > 0; o >>= 1) {
        sx += __shfl_down_sync(0xffffffffu, sx, o);
        sy += __shfl_down_sync(0xffffffffu, sy, o);
        sm += __shfl_down_sync(0xffffffffu, sm, o);
    }
    __shared__ double dsx[32], dsy[32], dsm[32];
    int wid = threadIdx.x >> 5, lid = threadIdx.x & 31;
    if (lid == 0) { dsx[wid] = sx; dsy[wid] = sy; dsm[wid] = sm; }
    __syncthreads();
    if (threadIdx.x == 0) {
        double tx = 0.0, ty = 0.0, tm = 0.0;
        #pragma unroll
        for (int w = 0; w < 32; ++w) { tx += dsx[w]; ty += dsy[w]; tm += dsm[w]; }
        g_target = make_float4((float)(tx / tm), (float)(ty / tm),
                               stiff[0] * 0.01f, 0.0f);
    }
}

// ---------------------------------------------------------------------------
// K3: vectorized epilogue, 2 bodies/thread (measured at the LTS cap).
// ---------------------------------------------------------------------------
__global__ void __launch_bounds__(256)
k3_apply(const float4* __restrict__ vel2,
         float4*       __restrict__ out2,
         int nhalf) {
    int i = blockIdx.x * blockDim.x + threadIdx.x;
    if (i >= nhalf) return;

    float4 t = g_target;                         // uniform broadcast
    unsigned int mw = g_mask[i >> 4];            // word for bodies 2i, 2i+1
    uint2  rc = ((const uint2*)g_rec)[i];
    float4 v  = vel2[i];

    int bit0 = (2 * i) & 31;
    {
        float ax = __half2float(__ushort_as_half((unsigned short)(rc.x & 0xffffu)));
        float ay = __half2float(__ushort_as_half((unsigned short)(rc.x >> 16)));
        float f  = ((mw >> bit0) & 1u) ? t.z : 0.0f;
        v.x = fmaf(f, t.x - ax, v.x);
        v.y = fmaf(f, t.y - ay, v.y);
    }
    {
        float ax = __half2float(__ushort_as_half((unsigned short)(rc.y & 0xffffu)));
        float ay = __half2float(__ushort_as_half((unsigned short)(rc.y >> 16)));
        float f  = ((mw >> (bit0 + 1)) & 1u) ? t.z : 0.0f;
        v.z = fmaf(f, t.x - ax, v.z);
        v.w = fmaf(f, t.y - ay, v.w);
    }
    out2[i] = v;
}

__global__ void __launch_bounds__(256)
k3_apply_tail(const float2* __restrict__ vel,
              float2*       __restrict__ out,
              int start, int n) {
    int b = start + blockIdx.x * blockDim.x + threadIdx.x;
    if (b >= n) return;
    float4 t = g_target;
    unsigned int rc = g_rec[b];
    float ax = __half2float(__ushort_as_half((unsigned short)(rc & 0xffffu)));
    float ay = __half2float(__ushort_as_half((unsigned short)(rc >> 16)));
    float f  = ((g_mask[b >> 5] >> (b & 31)) & 1u) ? t.z : 0.0f;
    float2 v = vel[b];
    v.x = fmaf(f, t.x - ax, v.x);
    v.y = fmaf(f, t.y - ay, v.y);
    out[b] = v;
}

// ---------------------------------------------------------------------------
// Inputs: from_bodies, to_bodies, from_bodies_position, to_bodies_position,
//         stiffness, position, angle, mass, velocity
// ---------------------------------------------------------------------------
extern "C" void kernel_launch(void* const* d_in, const int* in_sizes, int n_in,
                              void* d_out, int out_size) {
    const int*    fromb = (const int*)   d_in[0];
    const int*    tob   = (const int*)   d_in[1];
    const float2* fpos  = (const float2*)d_in[2];
    const float2* tpos  = (const float2*)d_in[3];
    const float*  stiff = (const float*) d_in[4];
    const float2* pos   = (const float2*)d_in[5];
    const float*  ang   = (const float*) d_in[6];
    const float*  mass  = (const float*) d_in[7];
    const float2* vel   = (const float2*)d_in[8];

    int nc = in_sizes[0];
    int n  = in_sizes[6];
    if (n > NBODY) n = NBODY;

    const int tpb = 256;
    int npair = (n + 1) >> 1;
    int nwork = npair;                       // KA covers pairs of bodies
    if (nc > nwork) nwork = nc;              // and pairs of endpoints (2*nc/2)
    int nba = (nwork + tpb - 1) / tpb;
    int half = n >> 1;
    int nb3  = (half + tpb - 1) / tpb;

    ka_build_scatter<<<nba, tpb>>>((const float4*)pos, (const float2*)ang,
                                   fpos, tpos,
                                   (const int2*)fromb, (const int2*)tob,
                                   n, nc);
    kb_sums<<<NPART, tpb>>>(mass, n);
    kc_finalize<<<1, 1024>>>(stiff, NPART);
    if (half > 0)
        k3_apply<<<nb3, tpb>>>((const float4*)vel, (float4*)d_out, half);
    if (n & 1)
        k3_apply_tail<<<1, tpb>>>(vel, (float2*)d_out, n - 1, n);
}